// round 16
// baseline (speedup 1.0000x reference)
#include <cuda_runtime.h>
#include <cuda_bf16.h>
#include <cstdint>

#define CC    512
#define HIDN  128
#define HWN   3136
#define NT    128
#define EPSV  1e-5f

// ---------------- precomputed weights (bf16 hi/lo) + folded BN ----------------
__device__ __nv_bfloat16 g_w1hi[2][HIDN * CC];
__device__ __nv_bfloat16 g_w1lo[2][HIDN * CC];
__device__ __nv_bfloat16 g_w2hi[2][CC * HIDN];
__device__ __nv_bfloat16 g_w2lo[2][CC * HIDN];
__device__ float g_scale[2][HIDN];
__device__ float g_shift[2][HIDN];

__global__ void prep_kernel(const float* __restrict__ w1_rgb, const float* __restrict__ w2_rgb,
                            const float* __restrict__ w1_inf, const float* __restrict__ w2_inf,
                            const float* __restrict__ rm_rgb, const float* __restrict__ rv_rgb,
                            const float* __restrict__ g_rgb,  const float* __restrict__ b_rgb,
                            const float* __restrict__ rm_inf, const float* __restrict__ rv_inf,
                            const float* __restrict__ g_inf,  const float* __restrict__ b_inf)
{
    int idx = blockIdx.x * blockDim.x + threadIdx.x;
    int seg = idx >> 16;
    int off = idx & 65535;
    const float* src;
    __nv_bfloat16 *dh, *dl;
    switch (seg) {
        case 0:  src = w1_rgb; dh = g_w1hi[1]; dl = g_w1lo[1]; break;
        case 1:  src = w1_inf; dh = g_w1hi[0]; dl = g_w1lo[0]; break;
        case 2:  src = w2_rgb; dh = g_w2hi[1]; dl = g_w2lo[1]; break;
        default: src = w2_inf; dh = g_w2hi[0]; dl = g_w2lo[0]; break;
    }
    float f = src[off];
    __nv_bfloat16 h = __float2bfloat16(f);
    dh[off] = h;
    dl[off] = __float2bfloat16(f - __bfloat162float(h));

    if (blockIdx.x == 0 && threadIdx.x < 256) {
        int i = threadIdx.x & 127;
        if (threadIdx.x < 128) {
            float s = g_rgb[i] * rsqrtf(rv_rgb[i] + EPSV);
            g_scale[1][i] = s;
            g_shift[1][i] = b_rgb[i] - rm_rgb[i] * s;
        } else {
            float s = g_inf[i] * rsqrtf(rv_inf[i] + EPSV);
            g_scale[0][i] = s;
            g_shift[0][i] = b_inf[i] - rm_inf[i] * s;
        }
    }
}

// ---------------- helpers ----------------
__device__ __forceinline__ uint32_t smem_u32(const void* p) {
    uint32_t a;
    asm("{ .reg .u64 t; cvta.to.shared.u64 t, %1; cvt.u32.u64 %0, t; }" : "=r"(a) : "l"(p));
    return a;
}
#define SW128(o) ((o) ^ ((((uint32_t)(o)) >> 3) & 0x70u))

__device__ __forceinline__ void ldsm4(uint32_t* r, uint32_t addr) {
    asm volatile("ldmatrix.sync.aligned.m8n8.x4.shared.b16 {%0,%1,%2,%3}, [%4];"
                 : "=r"(r[0]), "=r"(r[1]), "=r"(r[2]), "=r"(r[3]) : "r"(addr));
}
__device__ __forceinline__ void ldsm4t(uint32_t* r, uint32_t addr) {
    asm volatile("ldmatrix.sync.aligned.m8n8.x4.trans.shared.b16 {%0,%1,%2,%3}, [%4];"
                 : "=r"(r[0]), "=r"(r[1]), "=r"(r[2]), "=r"(r[3]) : "r"(addr));
}
__device__ __forceinline__ void mma_bf16(float* d, const uint32_t* a, const uint32_t* b) {
    asm volatile("mma.sync.aligned.m16n8k16.row.col.f32.bf16.bf16.f32 "
                 "{%0,%1,%2,%3}, {%4,%5,%6,%7}, {%8,%9}, {%0,%1,%2,%3};"
                 : "+f"(d[0]), "+f"(d[1]), "+f"(d[2]), "+f"(d[3])
                 : "r"(a[0]), "r"(a[1]), "r"(a[2]), "r"(a[3]), "r"(b[0]), "r"(b[1]));
}
__device__ __forceinline__ void cp16(uint32_t dst, const void* src) {
    asm volatile("cp.async.cg.shared.global [%0], [%1], 16;" :: "r"(dst), "l"(src));
}
#define CP_COMMIT() asm volatile("cp.async.commit_group;" ::: "memory")
#define CP_WAIT1()  asm volatile("cp.async.wait_group 1;" ::: "memory")

// ---------------- smem layout (bytes, dynamic), 3-stage pipeline ----------------
// [0,48K)        A stages: 3 x 16K (each: hi 8K [64 rows x 128B, two m-halves], lo 8K)
// [48K,96K)      xs stages: 3 x 16K (raw fp32 x chunk [32k x 128n], 512B rows)
// [96K,144K)     B stages: 3 x 16K (each: hi 8K = 2 x 64-col SW128 blocks, lo 8K)
// [144K,208K)    hs: hi 32K (2 x 16K 64-col blocks), lo 32K   [128k x 128n]
// [208K, ...)    sscale 512B | sshift 512B
#define OFF_A     0
#define OFF_XS    49152
#define OFF_B     98304
#define OFF_HS_HI 147456
#define OFF_HS_LO 180224
#define OFF_SCALE 212992
#define OFF_SHIFT 213504
#define SM_TOTAL  214016

struct Frags { uint32_t ah[2][4], al[2][4], bh[2][4], bl[2][4]; };

__device__ __forceinline__ void compute_chunk(
    const uint32_t sb, uint32_t abase, uint32_t bhibase, uint32_t blobase,
    uint32_t bstride, int brow0,
    int wm, int wn, int m_off, int ko_off, float acc[2][4][4])
{
    #pragma unroll
    for (int ks = 0; ks < 32; ks += 16) {
        Frags f;
        #pragma unroll
        for (int mt = 0; mt < 2; mt++) {
            int m = wm + mt * 16 + m_off;
            uint32_t o = SW128((uint32_t)(m & 63) * 128 + (m & 64) + (ks + ko_off) * 2);
            ldsm4(f.ah[mt], sb + abase + o);
            ldsm4(f.al[mt], sb + abase + 8192 + o);
        }
        #pragma unroll
        for (int bt = 0; bt < 2; bt++) {
            int bcolg = wn + bt * 16 + ko_off;
            uint32_t o = (uint32_t)(bcolg >> 6) * bstride
                       + SW128((uint32_t)(brow0 + ks + m_off) * 128 + (bcolg & 63) * 2);
            ldsm4t(f.bh[bt], sb + bhibase + o);
            ldsm4t(f.bl[bt], sb + blobase + o);
        }
        #pragma unroll
        for (int mt = 0; mt < 2; mt++)
            #pragma unroll
            for (int nt = 0; nt < 4; nt++) {
                const uint32_t* ph = &f.bh[nt >> 1][(nt & 1) * 2];
                const uint32_t* pl = &f.bl[nt >> 1][(nt & 1) * 2];
                mma_bf16(acc[mt][nt], f.ah[mt], ph);
                mma_bf16(acc[mt][nt], f.ah[mt], pl);
                mma_bf16(acc[mt][nt], f.al[mt], ph);
            }
    }
}

__global__ __launch_bounds__(512, 1)
void msp_pipe3(const float* __restrict__ x, const int* __restrict__ mod, float* __restrict__ out)
{
    extern __shared__ char smem[];
    const uint32_t sb = smem_u32(smem);
    const int tid  = threadIdx.x;
    const int wid  = tid >> 5;
    const int lane = tid & 31;
    const int b    = blockIdx.y;
    const int bx   = blockIdx.x;
    const int p0   = (bx == 24) ? (HWN - NT) : bx * NT;   // last tile overlaps (writes identical values)
    const int br   = (mod[b] == 1) ? 1 : 0;

    float* sscale = (float*)(smem + OFF_SCALE);
    float* sshift = (float*)(smem + OFF_SHIFT);
    if (tid < HIDN) {
        sscale[tid] = g_scale[br][tid];
        sshift[tid] = g_shift[br][tid];
    }

    const __nv_bfloat16* w1h = g_w1hi[br];
    const __nv_bfloat16* w1l = g_w1lo[br];
    const __nv_bfloat16* w2h = g_w2hi[br];
    const __nv_bfloat16* w2l = g_w2lo[br];
    const float* xb = x + ((size_t)b * CC) * HWN + p0;

    // 16 warps: 4 along M (32 rows each) x 4 along N (32 cols each)
    const int wm = (wid >> 2) * 32;
    const int wn = (wid & 3) * 32;
    const int lt = lane >> 3, lr = lane & 7;
    const int m_off  = (lt & 1) * 8 + lr;
    const int ko_off = (lt >> 1) * 8;

    // ---- chunk issue: chunks 0..15 = GEMM1 (W1 k-chunk + x chunk), 16..31 = GEMM2 (W2 chunk) ----
    auto issue_chunk = [&](int c) {
        const uint32_t abase = OFF_A + (uint32_t)(c % 3) * 16384;
        if (c < 16) {
            const int k0 = c * 32;
            #pragma unroll
            for (int i = 0; i < 2; i++) {
                int u = tid + i * 512;              // 0..1023 ; <512 = hi, >=512 = lo
                int m = (u & 511) >> 2, q = u & 3;
                const __nv_bfloat16* w = (u < 512) ? w1h : w1l;
                uint32_t dst = abase + ((u < 512) ? 0u : 8192u)
                             + SW128((uint32_t)(m & 63) * 128 + (m & 64) + q * 16);
                cp16(sb + dst, w + m * CC + k0 + q * 8);
            }
            const uint32_t xbase = OFF_XS + (uint32_t)(c % 3) * 16384;
            #pragma unroll
            for (int i = 0; i < 2; i++) {
                int u = tid + i * 512;              // 0..1023
                int r = u >> 5, q = u & 31;
                cp16(sb + xbase + r * 512 + q * 16, xb + (size_t)(k0 + r) * HWN + q * 4);
            }
        } else {
            const int j = c - 16, mc = j >> 2, kc = j & 3;
            #pragma unroll
            for (int i = 0; i < 2; i++) {
                int u = tid + i * 512;
                int m = (u & 511) >> 2, q = u & 3;
                const __nv_bfloat16* w = (u < 512) ? w2h : w2l;
                uint32_t dst = abase + ((u < 512) ? 0u : 8192u)
                             + SW128((uint32_t)(m & 63) * 128 + (m & 64) + q * 16);
                cp16(sb + dst, w + (mc * 128 + m) * HIDN + kc * 32 + q * 8);
            }
        }
        CP_COMMIT();
    };

    issue_chunk(0);
    issue_chunk(1);

    float acc[2][4][4];
    #pragma unroll
    for (int mt = 0; mt < 2; mt++)
        #pragma unroll
        for (int nt = 0; nt < 4; nt++)
            #pragma unroll
            for (int j = 0; j < 4; j++) acc[mt][nt][j] = 0.f;

    const int qr = lane >> 2, qc = (lane & 3) * 2;

    for (int c = 0; c < 32; c++) {
        CP_WAIT1();   // chunk c complete (c+1 may still be in flight)

        if (c < 16) {
            // convert x chunk c: fp32 staging -> bf16 hi/lo B buffers (SW128, 64-col blocks)
            const char* xs = smem + OFF_XS + (uint32_t)(c % 3) * 16384;
            char* bdst = smem + OFF_B + (uint32_t)(c % 3) * 16384;
            #pragma unroll
            for (int i = 0; i < 2; i++) {
                int u = tid + i * 512;             // 0..1023
                int r = u >> 5, c4 = (u & 31) * 4;
                float4 v = *(const float4*)(xs + r * 512 + c4 * 4);
                __nv_bfloat162 h01 = __floats2bfloat162_rn(v.x, v.y);
                __nv_bfloat162 h23 = __floats2bfloat162_rn(v.z, v.w);
                __nv_bfloat162 l01 = __floats2bfloat162_rn(v.x - __bfloat162float(h01.x),
                                                           v.y - __bfloat162float(h01.y));
                __nv_bfloat162 l23 = __floats2bfloat162_rn(v.z - __bfloat162float(h23.x),
                                                           v.w - __bfloat162float(h23.y));
                uint32_t off = (uint32_t)(c4 >> 6) * 4096 + SW128((uint32_t)r * 128 + (c4 & 63) * 2);
                *(uint2*)(bdst + off)        = make_uint2(*(uint32_t*)&h01, *(uint32_t*)&h23);
                *(uint2*)(bdst + 8192 + off) = make_uint2(*(uint32_t*)&l01, *(uint32_t*)&l23);
            }
        }

        __syncthreads();

        if (c == 16) {
            // GEMM1 epilogue: BN+ReLU, hi/lo split, write hs (accs hold full GEMM1 result)
            #pragma unroll
            for (int mt = 0; mt < 2; mt++)
                #pragma unroll
                for (int nt = 0; nt < 4; nt++) {
                    int r0 = wm + mt * 16 + qr;
                    int nc = wn + nt * 8 + qc;
                    float s0 = sscale[r0],     f0 = sshift[r0];
                    float s1 = sscale[r0 + 8], f1 = sshift[r0 + 8];
                    float v00 = fmaxf(fmaf(acc[mt][nt][0], s0, f0), 0.f);
                    float v01 = fmaxf(fmaf(acc[mt][nt][1], s0, f0), 0.f);
                    float v10 = fmaxf(fmaf(acc[mt][nt][2], s1, f1), 0.f);
                    float v11 = fmaxf(fmaf(acc[mt][nt][3], s1, f1), 0.f);
                    __nv_bfloat162 hp0 = __floats2bfloat162_rn(v00, v01);
                    __nv_bfloat162 lp0 = __floats2bfloat162_rn(v00 - __bfloat162float(hp0.x),
                                                               v01 - __bfloat162float(hp0.y));
                    __nv_bfloat162 hp1 = __floats2bfloat162_rn(v10, v11);
                    __nv_bfloat162 lp1 = __floats2bfloat162_rn(v10 - __bfloat162float(hp1.x),
                                                               v11 - __bfloat162float(hp1.y));
                    uint32_t blk = (uint32_t)(nc >> 6) * 16384;
                    uint32_t o0 = blk + SW128((uint32_t)r0 * 128 + (nc & 63) * 2);
                    uint32_t o1 = blk + SW128((uint32_t)(r0 + 8) * 128 + (nc & 63) * 2);
                    *(uint32_t*)(smem + OFF_HS_HI + o0) = *(uint32_t*)&hp0;
                    *(uint32_t*)(smem + OFF_HS_LO + o0) = *(uint32_t*)&lp0;
                    *(uint32_t*)(smem + OFF_HS_HI + o1) = *(uint32_t*)&hp1;
                    *(uint32_t*)(smem + OFF_HS_LO + o1) = *(uint32_t*)&lp1;
                }
            __syncthreads();
        }

        if (c + 2 < 32) issue_chunk(c + 2);
        else            CP_COMMIT();   // empty group keeps wait_group count invariant

        const uint32_t abase = OFF_A + (uint32_t)(c % 3) * 16384;
        if (c < 16) {
            const uint32_t bbase = OFF_B + (uint32_t)(c % 3) * 16384;
            compute_chunk(sb, abase, bbase, bbase + 8192, 4096, 0,
                          wm, wn, m_off, ko_off, acc);
        } else {
            const int j = c - 16, mc = j >> 2, kc = j & 3;
            if (kc == 0) {
                #pragma unroll
                for (int mt = 0; mt < 2; mt++)
                    #pragma unroll
                    for (int nt = 0; nt < 4; nt++)
                        #pragma unroll
                        for (int jj = 0; jj < 4; jj++) acc[mt][nt][jj] = 0.f;
            }
            compute_chunk(sb, abase, OFF_HS_HI, OFF_HS_LO, 16384, kc * 32,
                          wm, wn, m_off, ko_off, acc);
            if (kc == 3) {
                #pragma unroll
                for (int mt = 0; mt < 2; mt++)
                    #pragma unroll
                    for (int nt = 0; nt < 4; nt++) {
                        int m = mc * HIDN + wm + mt * 16 + qr;
                        float* orow = out + ((size_t)b * CC + m) * HWN + p0 + wn + nt * 8 + qc;
                        *(float2*)orow                     = make_float2(acc[mt][nt][0], acc[mt][nt][1]);
                        *(float2*)(orow + (size_t)8 * HWN) = make_float2(acc[mt][nt][2], acc[mt][nt][3]);
                    }
            }
        }
    }
}

extern "C" void kernel_launch(void* const* d_in, const int* in_sizes, int n_in,
                              void* d_out, int out_size)
{
    const float* x      = (const float*)d_in[0];
    const int*   mod    = (const int*)  d_in[1];
    const float* w1_rgb = (const float*)d_in[2];
    const float* rm_rgb = (const float*)d_in[3];
    const float* rv_rgb = (const float*)d_in[4];
    const float* g_rgb  = (const float*)d_in[5];
    const float* b_rgb  = (const float*)d_in[6];
    const float* w2_rgb = (const float*)d_in[7];
    const float* w1_inf = (const float*)d_in[8];
    const float* rm_inf = (const float*)d_in[9];
    const float* rv_inf = (const float*)d_in[10];
    const float* g_inf  = (const float*)d_in[11];
    const float* b_inf  = (const float*)d_in[12];
    const float* w2_inf = (const float*)d_in[13];
    float* out = (float*)d_out;

    const int B = in_sizes[1];

    prep_kernel<<<1024, 256>>>(w1_rgb, w2_rgb, w1_inf, w2_inf,
                               rm_rgb, rv_rgb, g_rgb, b_rgb,
                               rm_inf, rv_inf, g_inf, b_inf);

    cudaFuncSetAttribute(msp_pipe3, cudaFuncAttributeMaxDynamicSharedMemorySize, SM_TOTAL);
    dim3 grid(25, B);
    msp_pipe3<<<grid, 512, SM_TOTAL>>>(x, mod, out);
}